// round 2
// baseline (speedup 1.0000x reference)
#include <cuda_runtime.h>
#include <cuda_bf16.h>

#define NN 10000
#define NE 640000
#define FI 128
#define FH 128
#define FO 64

// ---------------- scratch (static __device__, no allocation) ----------------
__device__ int g_deg_in[NN];
__device__ int g_deg_out[NN];
__device__ int g_row_ptr[NN + 1];
__device__ int g_cursor[NN];
__device__ int g_csr[NE];
__device__ float g_rdi[NN];
__device__ float g_rdo[NN];
__device__ __align__(16) float g_t1[NN * FH];   // (x*rd_out)@W1
__device__ __align__(16) float g_h1[NN * FH];   // relu((S t1)*rd_in + b1)
__device__ __align__(16) float g_t2[NN * FO];   // (h1*rd_out)@W2

// ---------------- setup kernels ----------------
__global__ void k_zero() {
    int i = blockIdx.x * blockDim.x + threadIdx.x;
    if (i < NN) { g_deg_in[i] = 0; g_deg_out[i] = 0; }
}

__global__ void k_hist(const int* __restrict__ src, const int* __restrict__ dst) {
    for (int e = blockIdx.x * blockDim.x + threadIdx.x; e < NE; e += gridDim.x * blockDim.x) {
        int s = src[e], d = dst[e];
        if ((unsigned)s < NN) atomicAdd(&g_deg_out[s], 1);
        if ((unsigned)d < NN) atomicAdd(&g_deg_in[d], 1);
    }
}

// single-block scan over 10000 degrees -> row_ptr, cursors, rsqrt factors
__global__ void k_scan() {
    __shared__ int part[1024];
    const int tid = threadIdx.x;
    const int CH = 10;                 // 1024*10 >= 10000
    int base = tid * CH;
    int s = 0;
    #pragma unroll
    for (int i = 0; i < CH; i++) { int idx = base + i; if (idx < NN) s += g_deg_in[idx]; }
    part[tid] = s;
    __syncthreads();
    for (int off = 1; off < 1024; off <<= 1) {
        int v = (tid >= off) ? part[tid - off] : 0;
        __syncthreads();
        part[tid] += v;
        __syncthreads();
    }
    int run = (tid > 0) ? part[tid - 1] : 0;
    #pragma unroll
    for (int i = 0; i < CH; i++) {
        int idx = base + i;
        if (idx < NN) {
            g_row_ptr[idx] = run;
            g_cursor[idx] = run;
            int di = g_deg_in[idx];
            run += di;
            g_rdi[idx] = rsqrtf(fmaxf((float)di, 1.0f));
            g_rdo[idx] = rsqrtf(fmaxf((float)g_deg_out[idx], 1.0f));
        }
    }
    if (tid == 1023) g_row_ptr[NN] = part[1023];
}

__global__ void k_fill(const int* __restrict__ src, const int* __restrict__ dst) {
    for (int e = blockIdx.x * blockDim.x + threadIdx.x; e < NE; e += gridDim.x * blockDim.x) {
        int s = src[e], d = dst[e];
        if ((unsigned)d >= NN || (unsigned)s >= NN) continue;
        int p = atomicAdd(&g_cursor[d], 1);
        if (p < NE) g_csr[p] = s;
    }
}

// ---------------- GEMM: T[n, NW-cols] = rd_out[n] * (X[n,:128] @ W[:128, cols]) ---
// block = 128 threads, tile = 32 rows x 64 cols, thread = 4x4 register block
template <int NW>
__global__ void k_gemm(const float* __restrict__ X, const float* __restrict__ W,
                       float* __restrict__ T) {
    __shared__ float xs[32][128];      // 16 KB
    __shared__ float ws[128][64];      // 32 KB
    const int t = threadIdx.x;
    const int rowbase = blockIdx.x * 32;
    const int colbase = blockIdx.y * 64;

    // load W tile (128 x 64) via float4
    for (int i = t; i < 128 * 16; i += 128) {
        int k = i >> 4, c4 = i & 15;
        *(float4*)&ws[k][c4 * 4] = *(const float4*)&W[k * NW + colbase + c4 * 4];
    }
    // load X tile (32 x 128) with per-row rd_out scaling
    for (int i = t; i < 32 * 32; i += 128) {
        int r = i >> 5, c4 = i & 31;
        int row = rowbase + r;
        float4 v = make_float4(0.f, 0.f, 0.f, 0.f);
        float sc = 0.f;
        if (row < NN) { v = *(const float4*)&X[row * 128 + c4 * 4]; sc = g_rdo[row]; }
        v.x *= sc; v.y *= sc; v.z *= sc; v.w *= sc;
        *(float4*)&xs[r][c4 * 4] = v;
    }
    __syncthreads();

    const int tx = t & 15, ty = t >> 4;
    const int j0 = tx * 4, r0 = ty * 4;
    float4 acc[4];
    #pragma unroll
    for (int r = 0; r < 4; r++) acc[r] = make_float4(0.f, 0.f, 0.f, 0.f);

    #pragma unroll 4
    for (int k4 = 0; k4 < 32; k4++) {
        float4 a[4], w[4];
        #pragma unroll
        for (int r = 0; r < 4; r++) a[r] = *(float4*)&xs[r0 + r][k4 * 4];
        #pragma unroll
        for (int kk = 0; kk < 4; kk++) w[kk] = *(float4*)&ws[k4 * 4 + kk][j0];
        #pragma unroll
        for (int r = 0; r < 4; r++) {
            acc[r].x = fmaf(a[r].x, w[0].x, fmaf(a[r].y, w[1].x, fmaf(a[r].z, w[2].x, fmaf(a[r].w, w[3].x, acc[r].x))));
            acc[r].y = fmaf(a[r].x, w[0].y, fmaf(a[r].y, w[1].y, fmaf(a[r].z, w[2].y, fmaf(a[r].w, w[3].y, acc[r].y))));
            acc[r].z = fmaf(a[r].x, w[0].z, fmaf(a[r].y, w[1].z, fmaf(a[r].z, w[2].z, fmaf(a[r].w, w[3].z, acc[r].z))));
            acc[r].w = fmaf(a[r].x, w[0].w, fmaf(a[r].y, w[1].w, fmaf(a[r].z, w[2].w, fmaf(a[r].w, w[3].w, acc[r].w))));
        }
    }
    #pragma unroll
    for (int r = 0; r < 4; r++) {
        int row = rowbase + r0 + r;
        if (row < NN) *(float4*)&T[row * NW + colbase + j0] = acc[r];
    }
}

// ---------------- SpMM: warp-per-node gather-reduce ----------------
// layer 1: F=128, lane holds float4; fused rd_in scale + bias + relu -> h1
__global__ void k_spmm128(const float* __restrict__ T, const float* __restrict__ bias,
                          float* __restrict__ out) {
    int gw = (blockIdx.x * blockDim.x + threadIdx.x) >> 5;
    if (gw >= NN) return;
    int lane = threadIdx.x & 31;
    int c = lane * 4;
    int s = g_row_ptr[gw], e = g_row_ptr[gw + 1];
    float4 a0 = make_float4(0.f,0.f,0.f,0.f), a1 = a0, a2 = a0, a3 = a0;
    int i = s;
    for (; i + 4 <= e; i += 4) {
        int s0 = g_csr[i], s1 = g_csr[i + 1], s2 = g_csr[i + 2], s3 = g_csr[i + 3];
        float4 v0 = *(const float4*)(T + s0 * 128 + c);
        float4 v1 = *(const float4*)(T + s1 * 128 + c);
        float4 v2 = *(const float4*)(T + s2 * 128 + c);
        float4 v3 = *(const float4*)(T + s3 * 128 + c);
        a0.x += v0.x; a0.y += v0.y; a0.z += v0.z; a0.w += v0.w;
        a1.x += v1.x; a1.y += v1.y; a1.z += v1.z; a1.w += v1.w;
        a2.x += v2.x; a2.y += v2.y; a2.z += v2.z; a2.w += v2.w;
        a3.x += v3.x; a3.y += v3.y; a3.z += v3.z; a3.w += v3.w;
    }
    for (; i < e; i++) {
        int s0 = g_csr[i];
        float4 v = *(const float4*)(T + s0 * 128 + c);
        a0.x += v.x; a0.y += v.y; a0.z += v.z; a0.w += v.w;
    }
    float rd = g_rdi[gw];
    float4 b = *(const float4*)(bias + c);
    float4 o;
    o.x = fmaxf(fmaf((a0.x + a1.x) + (a2.x + a3.x), rd, b.x), 0.f);
    o.y = fmaxf(fmaf((a0.y + a1.y) + (a2.y + a3.y), rd, b.y), 0.f);
    o.z = fmaxf(fmaf((a0.z + a1.z) + (a2.z + a3.z), rd, b.z), 0.f);
    o.w = fmaxf(fmaf((a0.w + a1.w) + (a2.w + a3.w), rd, b.w), 0.f);
    *(float4*)(out + gw * 128 + c) = o;
}

// layer 2: F=64, lane holds float2; fused rd_in scale + bias (no relu) -> d_out
__global__ void k_spmm64(const float* __restrict__ T, const float* __restrict__ bias,
                         float* __restrict__ out) {
    int gw = (blockIdx.x * blockDim.x + threadIdx.x) >> 5;
    if (gw >= NN) return;
    int lane = threadIdx.x & 31;
    int c = lane * 2;
    int s = g_row_ptr[gw], e = g_row_ptr[gw + 1];
    float2 a0 = make_float2(0.f,0.f), a1 = a0, a2 = a0, a3 = a0;
    int i = s;
    for (; i + 4 <= e; i += 4) {
        int s0 = g_csr[i], s1 = g_csr[i + 1], s2 = g_csr[i + 2], s3 = g_csr[i + 3];
        float2 v0 = *(const float2*)(T + s0 * 64 + c);
        float2 v1 = *(const float2*)(T + s1 * 64 + c);
        float2 v2 = *(const float2*)(T + s2 * 64 + c);
        float2 v3 = *(const float2*)(T + s3 * 64 + c);
        a0.x += v0.x; a0.y += v0.y;
        a1.x += v1.x; a1.y += v1.y;
        a2.x += v2.x; a2.y += v2.y;
        a3.x += v3.x; a3.y += v3.y;
    }
    for (; i < e; i++) {
        int s0 = g_csr[i];
        float2 v = *(const float2*)(T + s0 * 64 + c);
        a0.x += v.x; a0.y += v.y;
    }
    float rd = g_rdi[gw];
    float2 b = *(const float2*)(bias + c);
    float2 o;
    o.x = fmaf((a0.x + a1.x) + (a2.x + a3.x), rd, b.x);
    o.y = fmaf((a0.y + a1.y) + (a2.y + a3.y), rd, b.y);
    *(float2*)(out + gw * 64 + c) = o;
}

// ---------------- launch ----------------
extern "C" void kernel_launch(void* const* d_in, const int* in_sizes, int n_in,
                              void* d_out, int out_size) {
    const float* x   = (const float*)d_in[0];
    const int*   src = (const int*)d_in[1];
    const int*   dst = (const int*)d_in[2];
    const float* W1  = (const float*)d_in[3];
    const float* b1  = (const float*)d_in[4];
    const float* W2  = (const float*)d_in[5];
    const float* b2  = (const float*)d_in[6];
    float* out = (float*)d_out;

    float *t1, *h1, *t2;
    cudaGetSymbolAddress((void**)&t1, g_t1);
    cudaGetSymbolAddress((void**)&h1, g_h1);
    cudaGetSymbolAddress((void**)&t2, g_t2);

    k_zero<<<(NN + 255) / 256, 256>>>();
    k_hist<<<512, 256>>>(src, dst);
    k_scan<<<1, 1024>>>();
    k_fill<<<512, 256>>>(src, dst);

    // layer 1: GEMM-first, then SpMM with fused scale+bias+relu
    k_gemm<FH><<<dim3((NN + 31) / 32, FH / 64), 128>>>(x, W1, t1);
    k_spmm128<<<(NN * 32 + 255) / 256, 256>>>(t1, b1, h1);

    // layer 2
    k_gemm<FO><<<dim3((NN + 31) / 32, FO / 64), 128>>>(h1, W2, t2);
    k_spmm64<<<(NN * 32 + 255) / 256, 256>>>(t2, b2, out);
}